// round 1
// baseline (speedup 1.0000x reference)
#include <cuda_runtime.h>

// BambooBase fused Coulomb(Ewald) + D3-CSO dispersion edge kernel.
// Inputs (metadata order):
//   d_in[0] row    int32  [E]
//   d_in[1] col    int32  [E]
//   d_in[2] dij    f32    [E,3]
//   d_in[3] charge f32    [N]
//   d_in[4] c6     f32    [N]
//   d_in[5] r0     f32    [N]
// Output (flat concat of reference tuple):
//   out[0      .. E)    ecoul
//   out[E      .. 4E)   coul_fij  [E,3]
//   out[4E     .. 5E)   edisp
//   out[5E     .. 8E)   disp_fij  [E,3]

__global__ __launch_bounds__(256) void bamboo_edge_kernel(
    const int* __restrict__ row,
    const int* __restrict__ col,
    const float* __restrict__ dij,
    const float* __restrict__ charge,
    const float* __restrict__ c6,
    const float* __restrict__ r0,
    float* __restrict__ out,
    int E)
{
    int i = blockIdx.x * blockDim.x + threadIdx.x;
    if (i >= E) return;

    const float ELE_FACTOR = 332.0637f;
    const float EWALD_F    = 1.12837917f;
    const float EWALD_P    = 0.3275911f;
    const float A0 = 0.254829592f, A1 = -0.284496736f, A2 = 1.421413741f,
                A3 = -1.453152027f, A4 = 1.061405429f;
    const float COUL_BETA  = 18.7f;
    const float COUL_R0    = 2.2f;
    const float INV_R0     = 1.0f / 2.2f;
    const float BETA_OVER_R0 = 18.7f / 2.2f;   // 8.5
    const float INV_BETA   = 1.0f / 18.7f;
    const float G_EWALD    = 0.3f;
    const float R6_SHIFT   = 8303.765625f;      // 4.5^6
    const float INV_CUT6   = 1.0e-6f;           // 1/10^6

    int r = row[i];
    int c = col[i];

    float dx = dij[3*i + 0];
    float dy = dij[3*i + 1];
    float dz = dij[3*i + 2];

    float r2   = dx*dx + dy*dy + dz*dz;
    float rinv = rsqrtf(r2);
    float rij  = r2 * rinv;          // rij = sqrt(r2)
    float rinv2 = rinv * rinv;

    // ---- Coulomb ----
    float qq = charge[r] * charge[c];
    float prefactor = ELE_FACTOR * qq * rinv;

    float x  = BETA_OVER_R0 * (rij - COUL_R0);        // in [-10.2, 66.3]
    float ex = __expf(x);
    float one_p_ex = 1.0f + ex;
    float damp = ex / one_p_ex;                        // sigmoid(x)
    float sp   = __logf(one_p_ex) * INV_BETA;          // softplus(beta*y)/beta
    float s    = rij * INV_R0 / (1.0f + sp);

    float ecoul = prefactor * s;
    float fcoul = prefactor * damp * s * s;

    float grij  = G_EWALD * rij;
    float expm2 = __expf(-grij * grij);
    float t     = 1.0f / (1.0f + EWALD_P * grij);
    float erfc  = t * (A0 + t * (A1 + t * (A2 + t * (A3 + t * A4)))) * expm2;

    ecoul += prefactor * (erfc - 1.0f);
    fcoul += prefactor * (erfc + EWALD_F * grij * expm2 - 1.0f);

    float cscale = fcoul * rinv2;    // fcoul / rij^2
    float cfx = dx * cscale;
    float cfy = dy * cscale;
    float cfz = dz * cscale;

    // ---- Dispersion (D3-CSO) ----
    float c6ij = sqrtf(c6[r] * c6[c]);
    float r0ij = 0.5f * (r0[r] + r0[c]);

    float r6pow = r2 * r2 * r2;                 // rij^6
    float r6    = r6pow + R6_SHIFT;
    float inv_r6 = 1.0f / r6;

    float e   = __expf(rij - 2.5f * r0ij);
    float inv_1pe = 1.0f / (1.0f + e);
    float cso = 0.85f + 0.82f * inv_1pe;

    float c6_inv_r6 = c6ij * inv_r6;
    float edisp = -c6_inv_r6 * cso;

    float r5 = r2 * r2 * rij;                   // rij^5
    float fdisp = -6.0f * c6ij * r5 * inv_r6 * inv_r6 * cso
                  - c6_inv_r6 * (0.82f * e * inv_1pe * inv_1pe);

    float dscale = fdisp * rinv;
    float dfx = dx * dscale;
    float dfy = dy * dscale;
    float dfz = dz * dscale;

    edisp += c6ij * INV_CUT6;

    // ---- stores ----
    long Eo = (long)E;
    out[i] = ecoul;
    out[Eo + 3*(long)i + 0] = cfx;
    out[Eo + 3*(long)i + 1] = cfy;
    out[Eo + 3*(long)i + 2] = cfz;
    out[4*Eo + i] = edisp;
    out[5*Eo + 3*(long)i + 0] = dfx;
    out[5*Eo + 3*(long)i + 1] = dfy;
    out[5*Eo + 3*(long)i + 2] = dfz;
}

extern "C" void kernel_launch(void* const* d_in, const int* in_sizes, int n_in,
                              void* d_out, int out_size)
{
    const int*   row    = (const int*)d_in[0];
    const int*   col    = (const int*)d_in[1];
    const float* dij    = (const float*)d_in[2];
    const float* charge = (const float*)d_in[3];
    const float* c6     = (const float*)d_in[4];
    const float* r0     = (const float*)d_in[5];
    float* out = (float*)d_out;

    int E = in_sizes[0];
    int threads = 256;
    int blocks = (E + threads - 1) / threads;
    bamboo_edge_kernel<<<blocks, threads>>>(row, col, dij, charge, c6, r0, out, E);
}

// round 2
// speedup vs baseline: 1.8662x; 1.8662x over previous
#include <cuda_runtime.h>

// BambooBase fused Coulomb(Ewald) + D3-CSO dispersion edge kernel.
// R2: pack atom data (charge, c6, r0) into one float4 gather per atom,
// pre-folding sqrt(ELE_FACTOR) into charge, sqrt into c6, and 1.25x into r0.
// This cuts the 6 random gathers/edge (dominant L1tex wavefront cost) to 2.

#define MAX_ATOMS 200064

__device__ float4 g_atom[MAX_ATOMS];

__global__ __launch_bounds__(256) void pack_atoms_kernel(
    const float* __restrict__ charge,
    const float* __restrict__ c6,
    const float* __restrict__ r0,
    int N)
{
    int i = blockIdx.x * blockDim.x + threadIdx.x;
    if (i >= N) return;
    const float SQRT_ELE = 18.222615f;   // sqrt(332.0637)
    float4 p;
    p.x = charge[i] * SQRT_ELE;
    p.y = sqrtf(c6[i]);
    p.z = 1.25f * r0[i];                 // so 2.5*r0ij = z_r + z_c
    p.w = 0.0f;
    g_atom[i] = p;
}

__global__ __launch_bounds__(256) void bamboo_edge_kernel(
    const int* __restrict__ row,
    const int* __restrict__ col,
    const float* __restrict__ dij,
    float* __restrict__ out,
    int E)
{
    int i = blockIdx.x * blockDim.x + threadIdx.x;
    if (i >= E) return;

    const float EWALD_F    = 1.12837917f;
    const float EWALD_P    = 0.3275911f;
    const float A0 = 0.254829592f, A1 = -0.284496736f, A2 = 1.421413741f,
                A3 = -1.453152027f, A4 = 1.061405429f;
    const float COUL_R0    = 2.2f;
    const float INV_R0     = 1.0f / 2.2f;
    const float BETA_OVER_R0 = 18.7f / 2.2f;   // 8.5
    const float INV_BETA   = 1.0f / 18.7f;
    const float G_EWALD    = 0.3f;
    const float R6_SHIFT   = 8303.765625f;      // 4.5^6
    const float INV_CUT6   = 1.0e-6f;           // 1/10^6

    int r = row[i];
    int c = col[i];

    float dx = dij[3*i + 0];
    float dy = dij[3*i + 1];
    float dz = dij[3*i + 2];

    float4 pa = g_atom[r];
    float4 pb = g_atom[c];

    float r2   = dx*dx + dy*dy + dz*dz;
    float rinv = rsqrtf(r2);
    float rij  = r2 * rinv;          // rij = sqrt(r2)
    float rinv2 = rinv * rinv;

    // ---- Coulomb ----
    float prefactor = pa.x * pb.x * rinv;      // ELE folded into charges

    float x  = BETA_OVER_R0 * (rij - COUL_R0);
    float ex = __expf(x);
    float one_p_ex = 1.0f + ex;
    float inv_1pex = 1.0f / one_p_ex;
    float damp = ex * inv_1pex;                        // sigmoid(x)
    float sp   = __logf(one_p_ex) * INV_BETA;          // softplus(beta*y)/beta
    float s    = rij * INV_R0 / (1.0f + sp);

    float ecoul = prefactor * s;
    float fcoul = prefactor * damp * s * s;

    float grij  = G_EWALD * rij;
    float expm2 = __expf(-grij * grij);
    float t     = 1.0f / (1.0f + EWALD_P * grij);
    float erfc  = t * (A0 + t * (A1 + t * (A2 + t * (A3 + t * A4)))) * expm2;

    ecoul += prefactor * (erfc - 1.0f);
    fcoul += prefactor * (erfc + EWALD_F * grij * expm2 - 1.0f);

    float cscale = fcoul * rinv2;    // fcoul / rij^2
    float cfx = dx * cscale;
    float cfy = dy * cscale;
    float cfz = dz * cscale;

    // ---- Dispersion (D3-CSO) ----
    float c6ij = pa.y * pb.y;                   // sqrt(c6r*c6c)

    float r6pow = r2 * r2 * r2;                 // rij^6
    float r6    = r6pow + R6_SHIFT;
    float inv_r6 = 1.0f / r6;

    float e   = __expf(rij - (pa.z + pb.z));    // rij - 2.5*r0ij
    float inv_1pe = 1.0f / (1.0f + e);
    float cso = 0.85f + 0.82f * inv_1pe;

    float c6_inv_r6 = c6ij * inv_r6;
    float edisp = -c6_inv_r6 * cso;

    float r5 = r2 * r2 * rij;                   // rij^5
    float fdisp = -6.0f * c6ij * r5 * inv_r6 * inv_r6 * cso
                  - c6_inv_r6 * (0.82f * e * inv_1pe * inv_1pe);

    float dscale = fdisp * rinv;
    float dfx = dx * dscale;
    float dfy = dy * dscale;
    float dfz = dz * dscale;

    edisp += c6ij * INV_CUT6;

    // ---- stores ----
    long Eo = (long)E;
    out[i] = ecoul;
    out[Eo + 3*(long)i + 0] = cfx;
    out[Eo + 3*(long)i + 1] = cfy;
    out[Eo + 3*(long)i + 2] = cfz;
    out[4*Eo + i] = edisp;
    out[5*Eo + 3*(long)i + 0] = dfx;
    out[5*Eo + 3*(long)i + 1] = dfy;
    out[5*Eo + 3*(long)i + 2] = dfz;
}

extern "C" void kernel_launch(void* const* d_in, const int* in_sizes, int n_in,
                              void* d_out, int out_size)
{
    const int*   row    = (const int*)d_in[0];
    const int*   col    = (const int*)d_in[1];
    const float* dij    = (const float*)d_in[2];
    const float* charge = (const float*)d_in[3];
    const float* c6     = (const float*)d_in[4];
    const float* r0     = (const float*)d_in[5];
    float* out = (float*)d_out;

    int E = in_sizes[0];
    int N = in_sizes[3];

    int threads = 256;
    pack_atoms_kernel<<<(N + threads - 1) / threads, threads>>>(charge, c6, r0, N);
    bamboo_edge_kernel<<<(E + threads - 1) / threads, threads>>>(row, col, dij, out, E);
}